// round 4
// baseline (speedup 1.0000x reference)
#include <cuda_runtime.h>
#include <cuda_bf16.h>

// AttentionAggregator: out[n] = softmax_k(feats[n,k]·w) weighted sum of feats[n,k]
// feats[n,k] = embed_table[neigh_idx[n,k]]  (gather, D=128, K=10)
//
// One warp per node. Lane owns dims {lane, lane+32, lane+64, lane+96}.
// Row gathers use 4x LDG.32 (1 cache line / 1 wavefront each) instead of
// LDG.128 (4 within-instruction replay wavefronts @2.07 cyc) — halves the
// L1tex port cost of the 512MB gather, which R3 ncu showed as the limiter.

#define K_NEIGH 10
#define D_DIM   128

__global__ __launch_bounds__(256, 4) void attn_agg_kernel(
    const float* __restrict__ table,   // [VOCAB, 128]
    const float* __restrict__ attn_w,  // [128]
    const int*  __restrict__ nidx,     // [N, 10] (int32)
    float* __restrict__ out,           // [N, 128]
    int n_nodes)
{
    int warp = (int)((blockIdx.x * (unsigned)blockDim.x + threadIdx.x) >> 5);
    int lane = threadIdx.x & 31;
    if (warp >= n_nodes) return;

    // attn_w for this lane's 4 strided dims
    const float w0 = __ldg(attn_w + lane);
    const float w1 = __ldg(attn_w + lane + 32);
    const float w2 = __ldg(attn_w + lane + 64);
    const float w3 = __ldg(attn_w + lane + 96);

    const int* ni = nidx + (long long)warp * K_NEIGH;

    float f0[K_NEIGH], f1[K_NEIGH], f2[K_NEIGH], f3[K_NEIGH];
    float s[K_NEIGH];

    // Gather: 4 scalar loads per row, each warp-access = one 128B line.
    #pragma unroll
    for (int k = 0; k < K_NEIGH; k++) {
        long long row = (long long)__ldg(ni + k);     // uniform broadcast
        const float* base = table + row * D_DIM + lane;
        f0[k] = __ldg(base);
        f1[k] = __ldg(base + 32);
        f2[k] = __ldg(base + 64);
        f3[k] = __ldg(base + 96);
    }

    #pragma unroll
    for (int k = 0; k < K_NEIGH; k++) {
        float p = f0[k] * w0 + f1[k] * w1 + f2[k] * w2 + f3[k] * w3;
        p += __shfl_xor_sync(0xffffffffu, p, 16);
        p += __shfl_xor_sync(0xffffffffu, p, 8);
        p += __shfl_xor_sync(0xffffffffu, p, 4);
        p += __shfl_xor_sync(0xffffffffu, p, 2);
        p += __shfl_xor_sync(0xffffffffu, p, 1);
        s[k] = p;
    }

    // softmax over K in registers
    float m = s[0];
    #pragma unroll
    for (int k = 1; k < K_NEIGH; k++) m = fmaxf(m, s[k]);
    float sum = 0.0f;
    #pragma unroll
    for (int k = 0; k < K_NEIGH; k++) { s[k] = __expf(s[k] - m); sum += s[k]; }
    float inv = __frcp_rn(sum);

    // weighted sum of register-resident feats
    float a0 = 0.f, a1 = 0.f, a2 = 0.f, a3 = 0.f;
    #pragma unroll
    for (int k = 0; k < K_NEIGH; k++) {
        float wk = s[k] * inv;
        a0 = fmaf(wk, f0[k], a0);
        a1 = fmaf(wk, f1[k], a1);
        a2 = fmaf(wk, f2[k], a2);
        a3 = fmaf(wk, f3[k], a3);
    }

    float* ob = out + (long long)warp * D_DIM + lane;
    ob[0]  = a0;
    ob[32] = a1;
    ob[64] = a2;
    ob[96] = a3;
}

extern "C" void kernel_launch(void* const* d_in, const int* in_sizes, int n_in,
                              void* d_out, int out_size)
{
    const float* table  = (const float*)d_in[0];  // [VOCAB*128]
    const float* attn_w = (const float*)d_in[1];  // [128]
    const int*   nidx   = (const int*)d_in[2];    // [N*10] int32

    int n_nodes = in_sizes[2] / K_NEIGH;
    float* out = (float*)d_out;

    const int threads = 256;               // 8 warps -> 8 nodes per block
    int blocks = (n_nodes + 7) / 8;
    attn_agg_kernel<<<blocks, threads>>>(table, attn_w, nidx, out, n_nodes);
}

// round 7
// speedup vs baseline: 1.0168x; 1.0168x over previous
#include <cuda_runtime.h>
#include <cuda_bf16.h>

// AttentionAggregator: out[n] = softmax_k(feats[n,k]·w) weighted sum of feats[n,k]
// feats[n,k] = embed_table[neigh_idx[n,k]]  (gather, D=128, K=10)
//
// One warp per node, lane owns 4 contiguous dims (float4).
// R5: minimize MEMORY-INSTRUCTION count (LSU 4-cyc LDG floor was the R3 limiter):
//   - 10 idx loads -> 1 cooperative LDG.32 + shfl broadcast
//   - feats: 10x LDG.128 (minimum)
//   - output: STG.128 with .cs streaming hint (don't evict the L2-resident table)

#define K_NEIGH 10
#define D_DIM   128

__global__ __launch_bounds__(256) void attn_agg_kernel(
    const float* __restrict__ table,   // [VOCAB, 128]
    const float* __restrict__ attn_w,  // [128]
    const int*  __restrict__ nidx,     // [N, 10] (int32)
    float* __restrict__ out,           // [N, 128]
    int n_nodes)
{
    int warp = (int)((blockIdx.x * (unsigned)blockDim.x + threadIdx.x) >> 5);
    int lane = threadIdx.x & 31;
    if (warp >= n_nodes) return;

    // attn_w slice for this lane's 4 dims
    const float4 w4 = __ldg(reinterpret_cast<const float4*>(attn_w) + lane);

    // One coalesced load covers all 10 indices (lanes 0..9), then broadcast.
    const int* ni = nidx + (long long)warp * K_NEIGH;
    int myidx = (lane < K_NEIGH) ? __ldg(ni + lane) : 0;

    float4 f[K_NEIGH];
    float  s[K_NEIGH];

    // Issue all 10 independent row gathers (MLP=10)
    #pragma unroll
    for (int k = 0; k < K_NEIGH; k++) {
        long long row = (long long)__shfl_sync(0xffffffffu, myidx, k);
        f[k] = __ldg(reinterpret_cast<const float4*>(table + row * D_DIM) + lane);
    }

    #pragma unroll
    for (int k = 0; k < K_NEIGH; k++) {
        float p = f[k].x * w4.x + f[k].y * w4.y + f[k].z * w4.z + f[k].w * w4.w;
        p += __shfl_xor_sync(0xffffffffu, p, 16);
        p += __shfl_xor_sync(0xffffffffu, p, 8);
        p += __shfl_xor_sync(0xffffffffu, p, 4);
        p += __shfl_xor_sync(0xffffffffu, p, 2);
        p += __shfl_xor_sync(0xffffffffu, p, 1);
        s[k] = p;
    }

    // softmax over K in registers
    float m = s[0];
    #pragma unroll
    for (int k = 1; k < K_NEIGH; k++) m = fmaxf(m, s[k]);
    float sum = 0.0f;
    #pragma unroll
    for (int k = 0; k < K_NEIGH; k++) { s[k] = __expf(s[k] - m); sum += s[k]; }
    float inv = __frcp_rn(sum);

    // weighted sum of register-resident feats
    float4 acc = make_float4(0.f, 0.f, 0.f, 0.f);
    #pragma unroll
    for (int k = 0; k < K_NEIGH; k++) {
        float wk = s[k] * inv;
        acc.x = fmaf(wk, f[k].x, acc.x);
        acc.y = fmaf(wk, f[k].y, acc.y);
        acc.z = fmaf(wk, f[k].z, acc.z);
        acc.w = fmaf(wk, f[k].w, acc.w);
    }

    // Streaming store: write-once output must not evict the embedding table from L2.
    __stcs(reinterpret_cast<float4*>(out + (long long)warp * D_DIM) + lane, acc);
}

extern "C" void kernel_launch(void* const* d_in, const int* in_sizes, int n_in,
                              void* d_out, int out_size)
{
    const float* table  = (const float*)d_in[0];  // [VOCAB*128]
    const float* attn_w = (const float*)d_in[1];  // [128]
    const int*   nidx   = (const int*)d_in[2];    // [N*10] int32

    int n_nodes = in_sizes[2] / K_NEIGH;
    float* out = (float*)d_out;

    const int threads = 256;               // 8 warps -> 8 nodes per block
    int blocks = (n_nodes + 7) / 8;
    attn_agg_kernel<<<blocks, threads>>>(table, attn_w, nidx, out, n_nodes);
}

// round 8
// speedup vs baseline: 1.1153x; 1.0969x over previous
#include <cuda_runtime.h>
#include <cuda_bf16.h>

// AttentionAggregator: out[n] = softmax_k(feats[n,k]·w) weighted sum of feats[n,k]
// feats[n,k] = embed_table[neigh_idx[n,k]]  (gather, D=128, K=10)
//
// One warp per node, lane owns 4 contiguous dims (float4).
// R8: gather via __ldcg (L2-only, bypass L1). The gather never hits L1 (random
// rows, 102MB table, per-launch L1 flush) yet L1 fill-wavefronts consumed a
// constant ~36.5us across R3/R4/R7 — the invariant limiter. Bypassing L1
// removes the fill/allocation half of that cost.
// Output via __stcs (write-once streaming, keep table resident in L2).

#define K_NEIGH 10
#define D_DIM   128

__global__ __launch_bounds__(256) void attn_agg_kernel(
    const float* __restrict__ table,   // [VOCAB, 128]
    const float* __restrict__ attn_w,  // [128]
    const int*  __restrict__ nidx,     // [N, 10] (int32)
    float* __restrict__ out,           // [N, 128]
    int n_nodes)
{
    int warp = (int)((blockIdx.x * (unsigned)blockDim.x + threadIdx.x) >> 5);
    int lane = threadIdx.x & 31;
    if (warp >= n_nodes) return;

    // attn_w slice for this lane's 4 dims
    const float4 w4 = __ldg(reinterpret_cast<const float4*>(attn_w) + lane);

    const int* ni = nidx + (long long)warp * K_NEIGH;

    float4 f[K_NEIGH];
    float  s[K_NEIGH];

    // Issue all 10 independent row gathers (MLP=10), L1-bypassed.
    #pragma unroll
    for (int k = 0; k < K_NEIGH; k++) {
        long long row = (long long)__ldg(ni + k);   // uniform broadcast
        f[k] = __ldcg(reinterpret_cast<const float4*>(table + row * D_DIM) + lane);
    }

    #pragma unroll
    for (int k = 0; k < K_NEIGH; k++) {
        float p = f[k].x * w4.x + f[k].y * w4.y + f[k].z * w4.z + f[k].w * w4.w;
        p += __shfl_xor_sync(0xffffffffu, p, 16);
        p += __shfl_xor_sync(0xffffffffu, p, 8);
        p += __shfl_xor_sync(0xffffffffu, p, 4);
        p += __shfl_xor_sync(0xffffffffu, p, 2);
        p += __shfl_xor_sync(0xffffffffu, p, 1);
        s[k] = p;
    }

    // softmax over K in registers
    float m = s[0];
    #pragma unroll
    for (int k = 1; k < K_NEIGH; k++) m = fmaxf(m, s[k]);
    float sum = 0.0f;
    #pragma unroll
    for (int k = 0; k < K_NEIGH; k++) { s[k] = __expf(s[k] - m); sum += s[k]; }
    float inv = __frcp_rn(sum);

    // weighted sum of register-resident feats
    float4 acc = make_float4(0.f, 0.f, 0.f, 0.f);
    #pragma unroll
    for (int k = 0; k < K_NEIGH; k++) {
        float wk = s[k] * inv;
        acc.x = fmaf(wk, f[k].x, acc.x);
        acc.y = fmaf(wk, f[k].y, acc.y);
        acc.z = fmaf(wk, f[k].z, acc.z);
        acc.w = fmaf(wk, f[k].w, acc.w);
    }

    // Streaming store: write-once output must not evict the table from L2.
    __stcs(reinterpret_cast<float4*>(out + (long long)warp * D_DIM) + lane, acc);
}

extern "C" void kernel_launch(void* const* d_in, const int* in_sizes, int n_in,
                              void* d_out, int out_size)
{
    const float* table  = (const float*)d_in[0];  // [VOCAB*128]
    const float* attn_w = (const float*)d_in[1];  // [128]
    const int*   nidx   = (const int*)d_in[2];    // [N*10] int32

    int n_nodes = in_sizes[2] / K_NEIGH;
    float* out = (float*)d_out;

    const int threads = 256;               // 8 warps -> 8 nodes per block
    int blocks = (n_nodes + 7) / 8;
    attn_agg_kernel<<<blocks, threads>>>(table, attn_w, nidx, out, n_nodes);
}